// round 1
// baseline (speedup 1.0000x reference)
#include <cuda_runtime.h>
#include <math.h>
#include <stddef.h>

#define EPSR 1e-8f
// 1/sqrt(1 + 1e-5)
#define BN_SCALE 0.99999500003749969f
#define LOG2PI 1.8378770664093454836f

// ---------------------------------------------------------------------------
// Scratch buffers (device globals; no allocation allowed)
// ---------------------------------------------------------------------------
__device__ float g_buf1 [32*256*14*14];  // conv1+bn out
__device__ float g_bufA [32*16*12*12];   // a (sigmoid(bn(conva)))
__device__ float g_bufP [32*256*12*12];  // pose (bn(convp))
__device__ float g_bufA2[32*16*6*6];     // EM1 a out
__device__ float g_bufP2[32*256*6*6];    // EM1 pose out (bnc1 fused)
__device__ float g_bufA3[32*16*6*6];     // EM2 a out
__device__ float g_bufP3[32*256*6*6];    // EM2 pose out (bnc2 fused)
__device__ float g_bufFC[32*25*10];      // EM3 a out per (b, l)

// ---------------------------------------------------------------------------
// conv1: x(32,3,32,32) * w(256,3,5,5) stride2 VALID -> (32,256,14,14), + bn
// grid (32, 16 co-tiles), block 224 = 16 co * 14 oy. Each thread: 14 ox.
// ---------------------------------------------------------------------------
__global__ void conv1_kernel(const float* __restrict__ x,
                             const float* __restrict__ w,
                             const float* __restrict__ g,
                             const float* __restrict__ b,
                             float* __restrict__ out)
{
    __shared__ float sIn[3*32*33];   // pitch 33 to avoid bank conflicts
    const int n = blockIdx.x, cot = blockIdx.y;
    const int tid = threadIdx.x;

    for (int idx = tid; idx < 3*32*32; idx += 224) {
        int ci = idx >> 10, rem = idx & 1023, r = rem >> 5, c = rem & 31;
        sIn[(ci*32 + r)*33 + c] = x[n*3072 + idx];
    }
    __syncthreads();

    const int co_l = tid / 14, oy = tid % 14;
    const int co = cot*16 + co_l;

    float acc[14];
#pragma unroll
    for (int i = 0; i < 14; i++) acc[i] = 0.f;

    const float* wp = w + co*75;
#pragma unroll
    for (int ci = 0; ci < 3; ci++) {
#pragma unroll
        for (int kh = 0; kh < 5; kh++) {
            const float* row = sIn + (ci*32 + oy*2 + kh)*33;
#pragma unroll
            for (int kw = 0; kw < 5; kw++) {
                float wv = wp[(ci*5 + kh)*5 + kw];
#pragma unroll
                for (int ox = 0; ox < 14; ox++)
                    acc[ox] = fmaf(wv, row[ox*2 + kw], acc[ox]);
            }
        }
    }
    const float sc = BN_SCALE * g[co], bi = b[co];
    float* op = out + (((size_t)n*256 + co)*14 + oy)*14;
#pragma unroll
    for (int ox = 0; ox < 14; ox++) op[ox] = acc[ox]*sc + bi;
}

// ---------------------------------------------------------------------------
// 3x3 conv over buf1 (N,CI=256,14,14) -> (N,CO,12,12), + bn (+sigmoid)
// grid (N, CO/16), block 192 = 16 co * 12 oy. Each thread: 12 ox.
// Dynamic smem: 64*196 floats per ci-chunk.
// ---------------------------------------------------------------------------
template<bool SIG>
__global__ void conv3_kernel(const float* __restrict__ in,
                             const float* __restrict__ w,
                             const float* __restrict__ g,
                             const float* __restrict__ bb,
                             float* __restrict__ out,
                             int CI, int CO)
{
    extern __shared__ float sIn[];   // 64*196
    const int n = blockIdx.x;
    const int tid = threadIdx.x;
    const int co_l = tid / 12, oy = tid % 12;
    const int co = blockIdx.y*16 + co_l;

    float acc[12];
#pragma unroll
    for (int i = 0; i < 12; i++) acc[i] = 0.f;

    for (int ci0 = 0; ci0 < CI; ci0 += 64) {
        __syncthreads();
        for (int idx = tid; idx < 64*196; idx += 192)
            sIn[idx] = in[((size_t)n*CI + ci0)*196 + idx];
        __syncthreads();

        for (int c = 0; c < 64; c++) {
            const float* wp = w + ((size_t)co*CI + ci0 + c)*9;
            float w9[9];
#pragma unroll
            for (int i = 0; i < 9; i++) w9[i] = wp[i];
#pragma unroll
            for (int kh = 0; kh < 3; kh++) {
                const float* row = sIn + (c*14 + oy + kh)*14;
                float rv[14];
#pragma unroll
                for (int i = 0; i < 14; i++) rv[i] = row[i];
#pragma unroll
                for (int kw = 0; kw < 3; kw++) {
                    float wv = w9[kh*3 + kw];
#pragma unroll
                    for (int ox = 0; ox < 12; ox++)
                        acc[ox] = fmaf(wv, rv[ox + kw], acc[ox]);
                }
            }
        }
    }
    const float sc = BN_SCALE * g[co], bi = bb[co];
    float* op = out + (((size_t)n*CO + co)*12 + oy)*12;
#pragma unroll
    for (int ox = 0; ox < 12; ox++) {
        float v = acc[ox]*sc + bi;
        if (SIG) v = 1.0f / (1.0f + expf(-v));
        op[ox] = v;
    }
}

// ---------------------------------------------------------------------------
// EM routing: one CTA per (batch n, output pixel l). Votes v live in smem.
// A_=input caps, PS=16, BB=output caps, KS=kernel, STR=stride, PD=pad,
// IH=input spatial, OH=output spatial.
// WPOSE: write pose_out with fused BN. FC: write a_out as (n,l,BB).
// ---------------------------------------------------------------------------
template<int A_, int PS, int BB, int KS, int STR, int PD, int IH, int OH,
         bool WPOSE, bool FC>
__global__ void em_kernel(const float* __restrict__ aIn,
                          const float* __restrict__ poseIn,
                          const float* __restrict__ Wm,    // (KS*KS*A_, BB, 4,4)
                          const float* __restrict__ bu,    // (BB)
                          const float* __restrict__ ba,    // (BB)
                          const float* __restrict__ bng,   // (BB*PS) or null
                          const float* __restrict__ bnb,
                          float* __restrict__ aOut,
                          float* __restrict__ poseOut)
{
    constexpr int KK  = KS*KS;
    constexpr int KKA = KK*A_;
    constexpr int VST = BB*PS + 1;   // odd stride -> conflict-free k-walk
    constexpr int RST = BB + 1;      // odd stride

    extern __shared__ float sm[];
    float* sv  = sm;                    // KKA*VST   votes
    float* sr  = sv  + KKA*VST;         // KKA*RST   r / coeff
    float* spt = sr  + KKA*RST;         // KKA*PS    pose patch
    float* sa  = spt + KKA*PS;          // KKA       a_in
    float* smu = sa  + KKA;             // BB*PS
    float* ssg = smu + BB*PS;           // BB*PS     sigma -> 1/(2 sigma)
    float* srs = ssg + BB*PS;           // BB        r_sum
    float* sao = srs + BB;              // BB        a_out
    float* sld = sao + BB;              // BB        sum_p log(sigma)

    const int lidx = blockIdx.x;
    const int oy = lidx / OH, ox = lidx % OH;
    const int n  = blockIdx.y;
    const int tid = threadIdx.x;
    const int NT  = blockDim.x;

    // Phase 0a: gather pose patch + a_in (zero-padded)
    for (int kidx = tid; kidx < KKA; kidx += NT) {
        const int kk = kidx / A_, ai = kidx % A_;
        const int ki = kk / KS, kj = kk % KS;
        const int iy = oy*STR + ki - PD, ix = ox*STR + kj - PD;
        if (iy >= 0 && iy < IH && ix >= 0 && ix < IH) {
            const float* pp = poseIn + (((size_t)n*A_*PS + ai*PS)*IH + iy)*IH + ix;
#pragma unroll
            for (int p = 0; p < PS; p++) spt[kidx*PS + p] = pp[(size_t)p*IH*IH];
            sa[kidx] = aIn[(((size_t)n*A_ + ai)*IH + iy)*IH + ix];
        } else {
#pragma unroll
            for (int p = 0; p < PS; p++) spt[kidx*PS + p] = 0.f;
            sa[kidx] = 0.f;
        }
    }
    __syncthreads();

    // Phase 0b: votes v[k][j] = pose4x4 @ W[k][j]; init r = 1/BB
    for (int t = tid; t < KKA*BB; t += NT) {
        const int kidx = t / BB, j = t % BB;
        const float* pm = spt + kidx*PS;
        const float* wj = Wm + ((size_t)kidx*BB + j)*16;
        float* vk = sv + kidx*VST + j*PS;
#pragma unroll
        for (int xi = 0; xi < 4; xi++) {
            float r0=0.f, r1=0.f, r2=0.f, r3=0.f;
#pragma unroll
            for (int y = 0; y < 4; y++) {
                float a = pm[xi*4 + y];
                r0 = fmaf(a, wj[y*4+0], r0);
                r1 = fmaf(a, wj[y*4+1], r1);
                r2 = fmaf(a, wj[y*4+2], r2);
                r3 = fmaf(a, wj[y*4+3], r3);
            }
            vk[xi*4+0]=r0; vk[xi*4+1]=r1; vk[xi*4+2]=r2; vk[xi*4+3]=r3;
        }
        sr[kidx*RST + j] = 1.0f / (float)BB;
    }
    __syncthreads();

    float p95 = 1.0f;
    for (int it = 0; it < 3; it++) {
        p95 *= 0.95f;
        const float lam = 0.01f * (1.0f - p95);

        // A: r_sum[j] = sum_k r*a
        if (tid < BB) {
            float s = 0.f;
            for (int k = 0; k < KKA; k++) s = fmaf(sr[k*RST + tid], sa[k], s);
            srs[tid] = s;
        }
        __syncthreads();

        // A2: coeff in place: r <- r*a / (rsum + eps)
        for (int t = tid; t < KKA*BB; t += NT) {
            int k = t / BB, j = t % BB;
            sr[k*RST + j] = sr[k*RST + j] * sa[k] / (srs[j] + EPSR);
        }
        __syncthreads();

        // B: mu[j][p] = sum_k coeff * v
        for (int t = tid; t < BB*PS; t += NT) {
            const int j = t / PS, p = t % PS;
            float m = 0.f;
            for (int k = 0; k < KKA; k++)
                m = fmaf(sr[k*RST + j], sv[k*VST + j*PS + p], m);
            smu[t] = m;
        }
        __syncthreads();

        // C: sigma[j][p] = sum_k coeff*(v-mu)^2 + eps
        for (int t = tid; t < BB*PS; t += NT) {
            const int j = t / PS, p = t % PS;
            const float mu = smu[t];
            float s = 0.f;
            for (int k = 0; k < KKA; k++) {
                float d = sv[k*VST + j*PS + p] - mu;
                s = fmaf(sr[k*RST + j], d*d, s);
            }
            ssg[t] = s + EPSR;
        }
        __syncthreads();

        // D: cost + a_out (+ logdet for phase E)
        if (tid < BB) {
            float sl = 0.f, c = 0.f;
            const float buj = bu[tid];
#pragma unroll
            for (int p = 0; p < PS; p++) {
                float lg = logf(ssg[tid*PS + p]);
                sl += lg;
                c  += buj + 0.5f*lg;
            }
            c *= srs[tid];
            sld[tid] = sl;
            sao[tid] = 1.0f / (1.0f + expf(-lam * (ba[tid] - c)));
        }
        __syncthreads();

        if (it < 2) {
            // invert sigma for quad form
            for (int t = tid; t < BB*PS; t += NT) ssg[t] = 0.5f / ssg[t];
            __syncthreads();

            // E: r[k][:] = softmax_j( ln_p + log(a_out+eps) )
            for (int k = tid; k < KKA; k += NT) {
                float lnp[BB];
                float mx = -1e30f;
#pragma unroll
                for (int j = 0; j < BB; j++) {
                    float q = 0.f;
                    const float* vv = sv + k*VST + j*PS;
#pragma unroll
                    for (int p = 0; p < PS; p++) {
                        float d = vv[p] - smu[j*PS + p];
                        q = fmaf(d*d, ssg[j*PS + p], q);
                    }
                    float val = -0.5f * ((float)PS * LOG2PI + sld[j]) - q
                                + logf(sao[j] + EPSR);
                    lnp[j] = val;
                    mx = fmaxf(mx, val);
                }
                float se = 0.f;
#pragma unroll
                for (int j = 0; j < BB; j++) { float e = expf(lnp[j] - mx); lnp[j] = e; se += e; }
                const float inv = 1.0f / se;
#pragma unroll
                for (int j = 0; j < BB; j++) sr[k*RST + j] = lnp[j] * inv;
            }
            __syncthreads();
        }
    }

    // Outputs
    if (WPOSE) {
        for (int t = tid; t < BB*PS; t += NT) {
            poseOut[(((size_t)n*BB*PS + t)*OH + oy)*OH + ox] =
                smu[t]*BN_SCALE*bng[t] + bnb[t];
        }
    }
    if (tid < BB) {
        if (FC)
            aOut[((size_t)n*(OH*OH) + lidx)*BB + tid] = sao[tid];
        else
            aOut[(((size_t)n*BB + tid)*OH + oy)*OH + ox] = sao[tid];
    }
}

// ---------------------------------------------------------------------------
// Final: out[n,j] = mean over 25 spatial positions of EM3 activations
// ---------------------------------------------------------------------------
__global__ void reduce_kernel(const float* __restrict__ afc, float* __restrict__ out)
{
    const int t = blockIdx.x*blockDim.x + threadIdx.x;
    if (t < 320) {
        const int n = t / 10, j = t % 10;
        float s = 0.f;
        for (int l = 0; l < 25; l++) s += afc[(n*25 + l)*10 + j];
        out[t] = s * (1.0f/25.0f);
    }
}

// ---------------------------------------------------------------------------
extern "C" void kernel_launch(void* const* d_in, const int* in_sizes, int n_in,
                              void* d_out, int out_size)
{
    const float* x       = (const float*)d_in[0];
    const float* conv1_w = (const float*)d_in[1];
    const float* bn1_g   = (const float*)d_in[2];
    const float* bn1_b   = (const float*)d_in[3];
    const float* conva_w = (const float*)d_in[4];
    const float* bna_g   = (const float*)d_in[5];
    const float* bna_b   = (const float*)d_in[6];
    const float* convp_w = (const float*)d_in[7];
    const float* bnp_g   = (const float*)d_in[8];
    const float* bnp_b   = (const float*)d_in[9];
    const float* W1      = (const float*)d_in[10];
    const float* bu1     = (const float*)d_in[11];
    const float* ba1     = (const float*)d_in[12];
    const float* bnc1_g  = (const float*)d_in[13];
    const float* bnc1_b  = (const float*)d_in[14];
    const float* W2      = (const float*)d_in[15];
    const float* bu2     = (const float*)d_in[16];
    const float* ba2     = (const float*)d_in[17];
    const float* bnc2_g  = (const float*)d_in[18];
    const float* bnc2_b  = (const float*)d_in[19];
    const float* Wfc     = (const float*)d_in[20];
    const float* bufc    = (const float*)d_in[21];
    const float* bafc    = (const float*)d_in[22];

    float *buf1, *bufA, *bufP, *bufA2, *bufP2, *bufA3, *bufP3, *bufFC;
    cudaGetSymbolAddress((void**)&buf1,  g_buf1);
    cudaGetSymbolAddress((void**)&bufA,  g_bufA);
    cudaGetSymbolAddress((void**)&bufP,  g_bufP);
    cudaGetSymbolAddress((void**)&bufA2, g_bufA2);
    cudaGetSymbolAddress((void**)&bufP2, g_bufP2);
    cudaGetSymbolAddress((void**)&bufA3, g_bufA3);
    cudaGetSymbolAddress((void**)&bufP3, g_bufP3);
    cudaGetSymbolAddress((void**)&bufFC, g_bufFC);

    // conv1 + bn
    conv1_kernel<<<dim3(32,16), 224>>>(x, conv1_w, bn1_g, bn1_b, buf1);

    // conva (sigmoid) + convp
    const size_t c3smem = 64*196*sizeof(float);
    cudaFuncSetAttribute(conv3_kernel<true>,  cudaFuncAttributeMaxDynamicSharedMemorySize, (int)c3smem);
    cudaFuncSetAttribute(conv3_kernel<false>, cudaFuncAttributeMaxDynamicSharedMemorySize, (int)c3smem);
    conv3_kernel<true ><<<dim3(32,1),  192, c3smem>>>(buf1, conva_w, bna_g, bna_b, bufA, 256, 16);
    conv3_kernel<false><<<dim3(32,16), 192, c3smem>>>(buf1, convp_w, bnp_g, bnp_b, bufP, 256, 256);

    // EM1: 12x12 -> 6x6, k=3 s=2 p=1, A=16 B=16   (bnc1 fused into pose write)
    {
        constexpr int KKA = 9*16, VST = 16*16+1, RST = 17;
        const size_t sm1 = (size_t)(KKA*VST + KKA*RST + KKA*16 + KKA
                                    + 16*16 + 16*16 + 16 + 16 + 16) * sizeof(float);
        auto fn = em_kernel<16,16,16,3,2,1,12,6,true,false>;
        cudaFuncSetAttribute(fn, cudaFuncAttributeMaxDynamicSharedMemorySize, (int)sm1);
        fn<<<dim3(36,32), 256, sm1>>>(bufA, bufP, W1, bu1, ba1, bnc1_g, bnc1_b, bufA2, bufP2);
    }

    // EM2: 6x6 -> 6x6, k=3 s=1 p=1, A=16 B=16   (bnc2 fused)
    {
        constexpr int KKA = 9*16, VST = 16*16+1, RST = 17;
        const size_t sm2 = (size_t)(KKA*VST + KKA*RST + KKA*16 + KKA
                                    + 16*16 + 16*16 + 16 + 16 + 16) * sizeof(float);
        auto fn = em_kernel<16,16,16,3,1,1,6,6,true,false>;
        cudaFuncSetAttribute(fn, cudaFuncAttributeMaxDynamicSharedMemorySize, (int)sm2);
        fn<<<dim3(36,32), 256, sm2>>>(bufA2, bufP2, W2, bu2, ba2, bnc2_g, bnc2_b, bufA3, bufP3);
    }

    // EM3 (class caps): 6x6 -> 5x5, k=4 s=1 p=1, A=16 B=10, no pose out
    {
        constexpr int KKA = 16*16, VST = 10*16+1, RST = 11;
        const size_t sm3 = (size_t)(KKA*VST + KKA*RST + KKA*16 + KKA
                                    + 10*16 + 10*16 + 10 + 10 + 10) * sizeof(float);
        auto fn = em_kernel<16,16,10,4,1,1,6,5,false,true>;
        cudaFuncSetAttribute(fn, cudaFuncAttributeMaxDynamicSharedMemorySize, (int)sm3);
        fn<<<dim3(25,32), 256, sm3>>>(bufA3, bufP3, Wfc, bufc, bafc, nullptr, nullptr, bufFC, nullptr);
    }

    // mean over spatial
    reduce_kernel<<<1, 320>>>(bufFC, (float*)d_out);
}